// round 1
// baseline (speedup 1.0000x reference)
#include <cuda_runtime.h>

#define NTOK 8192
#define DIM 128
#define ODIM 128
#define OT 16
#define THREADS 256

// scratch (device globals: no allocation allowed in kernel_launch)
__device__ float g_xnorm[NTOK * DIM];
__device__ float g_pa[ODIM * DIM];
__device__ float g_pb[ODIM * DIM];
__device__ float g_pc1[ODIM * DIM];
__device__ float g_pc2[ODIM * DIM];

__device__ __forceinline__ float ex2f(float a) {
    float r;
    asm("ex2.approx.ftz.f32 %0, %1;" : "=f"(r) : "f"(a));
    return r;
}

// ---------------- LayerNorm: one warp per token row ----------------
__global__ void ln_kernel(const float* __restrict__ x,
                          const float* __restrict__ gamma,
                          const float* __restrict__ beta) {
    int gwarp = (blockIdx.x * blockDim.x + threadIdx.x) >> 5;
    int lane = threadIdx.x & 31;
    if (gwarp >= NTOK) return;
    float4 v = ((const float4*)(x + (size_t)gwarp * DIM))[lane];
    float s = (v.x + v.y) + (v.z + v.w);
    #pragma unroll
    for (int off = 16; off; off >>= 1) s += __shfl_xor_sync(0xffffffffu, s, off);
    float mu = s * (1.0f / DIM);
    float dx = v.x - mu, dy = v.y - mu, dz = v.z - mu, dw = v.w - mu;
    float q = (dx * dx + dy * dy) + (dz * dz + dw * dw);
    #pragma unroll
    for (int off = 16; off; off >>= 1) q += __shfl_xor_sync(0xffffffffu, q, off);
    float r = rsqrtf(q * (1.0f / DIM) + 1e-5f);
    float4 g = ((const float4*)gamma)[lane];
    float4 b = ((const float4*)beta)[lane];
    float4 o;
    o.x = fmaf(dx * r, g.x, b.x);
    o.y = fmaf(dy * r, g.y, b.y);
    o.z = fmaf(dz * r, g.z, b.z);
    o.w = fmaf(dw * r, g.w, b.w);
    ((float4*)g_xnorm)[(size_t)gwarp * (DIM / 4) + lane] = o;
}

// ---------------- Parameter folding ----------------
// s = softplus(scale)+0.1
// A  = SQ/s            SQ = sqrt(0.5*log2(e))  -> z' = z_true*SQ
// B  = -t*SQ/s
// nu = -z'^2 = -(0.5*log2 e)*z_true^2 ; e = 2^nu = exp(-z_true^2/2)
// C1 = MEX_C * ww ; C2 = C1 * 2ln2  (so fma(nu,-C2,-C1) = C1*(z_true^2 - 1))
__global__ void prep_kernel(const float* __restrict__ scale,
                            const float* __restrict__ trans,
                            const float* __restrict__ ww) {
    int i = blockIdx.x * blockDim.x + threadIdx.x;
    if (i >= ODIM * DIM) return;
    float sc = scale[i];
    float sp = (sc > 20.0f) ? sc : log1pf(expf(sc));
    float inv = 1.0f / (sp + 0.1f);
    const float SQ = 0.84932180f;      // sqrt(0.72134752)
    g_pa[i] = inv * SQ;
    g_pb[i] = -trans[i] * inv * SQ;
    float c1 = 0.86732507f * ww[i];    // MEX_C * ww
    g_pc1[i] = c1;
    g_pc2[i] = c1 * 1.38629436f;       // c1 * 2 ln 2
}

// ---------------- Main fused kernel ----------------
// lane -> token n (param loads are warp-uniform smem broadcasts)
// each thread: 16 wavelet accs + 16 base accs over its OT o-slice
__global__ __launch_bounds__(THREADS, 2)
void wave_kernel(const float* __restrict__ x,
                 const float* __restrict__ bw,
                 float* __restrict__ out) {
    __shared__ float4 sA[OT][DIM / 4];
    __shared__ float4 sB[OT][DIM / 4];
    __shared__ float4 sC1[OT][DIM / 4];
    __shared__ float4 sC2[OT][DIM / 4];
    __shared__ float4 sW[OT][DIM / 4];

    int o0 = blockIdx.y * OT;
    int tid = threadIdx.x;
    {
        const float4* pa  = (const float4*)(g_pa  + o0 * DIM);
        const float4* pb  = (const float4*)(g_pb  + o0 * DIM);
        const float4* pc1 = (const float4*)(g_pc1 + o0 * DIM);
        const float4* pc2 = (const float4*)(g_pc2 + o0 * DIM);
        const float4* pw  = (const float4*)(bw    + o0 * DIM);
        for (int i = tid; i < OT * (DIM / 4); i += THREADS) {
            ((float4*)sA)[i]  = pa[i];
            ((float4*)sB)[i]  = pb[i];
            ((float4*)sC1)[i] = pc1[i];
            ((float4*)sC2)[i] = pc2[i];
            ((float4*)sW)[i]  = pw[i];
        }
    }
    __syncthreads();

    int n = blockIdx.x * THREADS + tid;
    const float4* xn4 = (const float4*)(g_xnorm + (size_t)n * DIM);
    const float4* xr4 = (const float4*)(x + (size_t)n * DIM);

    float accw[OT], accb[OT];
    #pragma unroll
    for (int o = 0; o < OT; o++) { accw[o] = 0.0f; accb[o] = 0.0f; }

    #define WBODY(XN, XR, AA, BB, CC1, CC2, WWv, OI)                       \
        {                                                                  \
            float z = fmaf((XN), (AA), (BB));                              \
            float nu = z * (-z);                                           \
            float e = ex2f(nu);                                            \
            float p = fmaf(nu, -(CC2), -(CC1));                            \
            accw[OI] = fmaf(p, e, accw[OI]);                               \
            accb[OI] = fmaf((XR), (WWv), accb[OI]);                        \
        }

    for (int dc = 0; dc < DIM / 4; dc++) {
        float4 xn = xn4[dc];
        float4 xr = xr4[dc];
        #pragma unroll
        for (int o = 0; o < OT; o++) {
            float4 A  = sA[o][dc];
            float4 B  = sB[o][dc];
            float4 C1 = sC1[o][dc];
            float4 C2 = sC2[o][dc];
            float4 W  = sW[o][dc];
            WBODY(xn.x, xr.x, A.x, B.x, C1.x, C2.x, W.x, o)
            WBODY(xn.y, xr.y, A.y, B.y, C1.y, C2.y, W.y, o)
            WBODY(xn.z, xr.z, A.z, B.z, C1.z, C2.z, W.z, o)
            WBODY(xn.w, xr.w, A.w, B.w, C1.w, C2.w, W.w, o)
        }
    }
    #undef WBODY

    float* op = out + (size_t)n * ODIM + o0;
    #pragma unroll
    for (int o = 0; o < OT; o++) {
        float b = accb[o];
        float sig = 1.0f / (1.0f + ex2f(-1.44269504f * b));
        op[o] = fmaf(b, sig, accw[o]);
    }
}

extern "C" void kernel_launch(void* const* d_in, const int* in_sizes, int n_in,
                              void* d_out, int out_size) {
    const float* x     = (const float*)d_in[0];
    const float* scale = (const float*)d_in[1];
    const float* trans = (const float*)d_in[2];
    const float* ww    = (const float*)d_in[3];
    const float* bw    = (const float*)d_in[4];
    const float* gamma = (const float*)d_in[5];
    const float* beta  = (const float*)d_in[6];
    float* out = (float*)d_out;

    prep_kernel<<<(ODIM * DIM + 255) / 256, 256>>>(scale, trans, ww);
    ln_kernel<<<NTOK / 8, 256>>>(x, gamma, beta);
    dim3 grid(NTOK / THREADS, ODIM / OT);
    wave_kernel<<<grid, THREADS>>>(x, bw, out);
}

// round 2
// speedup vs baseline: 1.0892x; 1.0892x over previous
#include <cuda_runtime.h>

#define NTOK 8192
#define DIM 128
#define ODIM 128
#define OT 16
#define THREADS 256

typedef unsigned long long u64;

__device__ __forceinline__ float2 ffma2(float2 a, float2 b, float2 c) {
    float2 d;
    asm("fma.rn.f32x2 %0, %1, %2, %3;"
        : "=l"(reinterpret_cast<u64&>(d))
        : "l"(reinterpret_cast<u64 const&>(a)),
          "l"(reinterpret_cast<u64 const&>(b)),
          "l"(reinterpret_cast<u64 const&>(c)));
    return d;
}
__device__ __forceinline__ float2 fmul2(float2 a, float2 b) {
    float2 d;
    asm("mul.rn.f32x2 %0, %1, %2;"
        : "=l"(reinterpret_cast<u64&>(d))
        : "l"(reinterpret_cast<u64 const&>(a)),
          "l"(reinterpret_cast<u64 const&>(b)));
    return d;
}
__device__ __forceinline__ float2 fadd2(float2 a, float2 b) {
    float2 d;
    asm("add.rn.f32x2 %0, %1, %2;"
        : "=l"(reinterpret_cast<u64&>(d))
        : "l"(reinterpret_cast<u64 const&>(a)),
          "l"(reinterpret_cast<u64 const&>(b)));
    return d;
}
__device__ __forceinline__ float ex2f(float a) {
    float r; asm("ex2.approx.ftz.f32 %0, %1;" : "=f"(r) : "f"(a)); return r;
}

// w(z) = C(z^2-1)exp(-z^2/2),  z = (x_norm - t)/s
// nu = -H*z^2 with H = 0.5*log2(e)  ->  exp(-z^2/2) = 2^nu = ex2(nu)
// Per (o,d) folded params:
//   T  = -t
//   P  = -H/s^2            (nu = P*(x-t)^2, always <= 0)
//   C1n= -C*ww
//   C2n= -C*ww/H           (p = fma(nu, C2n, C1n) = C*ww*(z^2-1))
//   W  = base_w
__global__ __launch_bounds__(THREADS, 2)
void wavekan_fused(const float* __restrict__ x,
                   const float* __restrict__ scale,
                   const float* __restrict__ trans,
                   const float* __restrict__ ww,
                   const float* __restrict__ bw,
                   const float* __restrict__ gamma,
                   const float* __restrict__ beta,
                   float* __restrict__ out) {
    __shared__ float4 sT [OT][DIM / 4];
    __shared__ float4 sP [OT][DIM / 4];
    __shared__ float4 sC1[OT][DIM / 4];
    __shared__ float4 sC2[OT][DIM / 4];
    __shared__ float4 sW [OT][DIM / 4];
    __shared__ float4 sG [DIM / 4];
    __shared__ float4 sBt[DIM / 4];

    const int o0 = blockIdx.y * OT;
    const int tid = threadIdx.x;

    // ---- fold params for this o-tile into smem ----
    #pragma unroll
    for (int k = 0; k < (OT * DIM) / THREADS; k++) {
        int i = tid + k * THREADS;
        int gi = o0 * DIM + i;
        float sc = scale[gi];
        float sp = (sc > 20.0f) ? sc : log1pf(expf(sc));
        float s = sp + 0.1f;
        float inv2 = 1.0f / (s * s);
        float c1 = 0.86732507f * ww[gi];           // MEX_C * ww
        ((float*)sT)[i]  = -trans[gi];
        ((float*)sP)[i]  = -0.72134752f * inv2;    // -H/s^2
        ((float*)sC1)[i] = -c1;
        ((float*)sC2)[i] = -c1 * 1.38629436f;      // -c1/H
        ((float*)sW)[i]  = bw[gi];
    }
    if (tid < DIM / 4) {
        sG[tid]  = ((const float4*)gamma)[tid];
        sBt[tid] = ((const float4*)beta)[tid];
    }

    // ---- per-thread LayerNorm stats for token n (before sync; independent) ----
    const int n = blockIdx.x * THREADS + tid;
    const float4* xr4 = (const float4*)(x + (size_t)n * DIM);
    float sm = 0.0f, sq = 0.0f;
    #pragma unroll 4
    for (int dc = 0; dc < DIM / 4; dc++) {
        float4 v = xr4[dc];
        sm += (v.x + v.y) + (v.z + v.w);
        sq += (v.x * v.x + v.y * v.y) + (v.z * v.z + v.w * v.w);
    }
    float mu = sm * (1.0f / DIM);
    float var = fmaf(-mu, mu, sq * (1.0f / DIM));
    float rst = rsqrtf(var + 1e-5f);

    __syncthreads();

    const float2 r2   = make_float2(rst, rst);
    const float2 nmu2 = make_float2(-mu, -mu);

    float2 accw[OT];
    float  accb[OT];
    #pragma unroll
    for (int o = 0; o < OT; o++) { accw[o] = make_float2(0.0f, 0.0f); accb[o] = 0.0f; }

    for (int dc = 0; dc < DIM / 4; dc++) {
        float4 xv = xr4[dc];                      // L1-resident after pre-pass
        float4 g4 = sG[dc];
        float4 b4 = sBt[dc];
        // xn = x*(r*g) + (beta - mu*r*g), packed over d-pairs
        float2 rg_lo = fmul2(make_float2(g4.x, g4.y), r2);
        float2 rg_hi = fmul2(make_float2(g4.z, g4.w), r2);
        float2 c_lo  = ffma2(rg_lo, nmu2, make_float2(b4.x, b4.y));
        float2 c_hi  = ffma2(rg_hi, nmu2, make_float2(b4.z, b4.w));
        float2 x_lo  = make_float2(xv.x, xv.y);
        float2 x_hi  = make_float2(xv.z, xv.w);
        float2 xn_lo = ffma2(x_lo, rg_lo, c_lo);
        float2 xn_hi = ffma2(x_hi, rg_hi, c_hi);

        #pragma unroll
        for (int o = 0; o < OT; o++) {
            float4 T4  = sT [o][dc];
            float4 P4  = sP [o][dc];
            float4 C14 = sC1[o][dc];
            float4 C24 = sC2[o][dc];
            float4 W4  = sW [o][dc];

            // low pair
            {
                float2 y  = fadd2(xn_lo, make_float2(T4.x, T4.y));
                float2 yq = fmul2(y, y);
                float2 nu = fmul2(yq, make_float2(P4.x, P4.y));
                float2 e  = make_float2(ex2f(nu.x), ex2f(nu.y));
                float2 p  = ffma2(nu, make_float2(C24.x, C24.y),
                                      make_float2(C14.x, C14.y));
                accw[o] = ffma2(p, e, accw[o]);
            }
            // high pair
            {
                float2 y  = fadd2(xn_hi, make_float2(T4.z, T4.w));
                float2 yq = fmul2(y, y);
                float2 nu = fmul2(yq, make_float2(P4.z, P4.w));
                float2 e  = make_float2(ex2f(nu.x), ex2f(nu.y));
                float2 p  = ffma2(nu, make_float2(C24.z, C24.w),
                                      make_float2(C14.z, C14.w));
                accw[o] = ffma2(p, e, accw[o]);
            }
            // base GEMM on raw x (scalar FFMAs)
            float bb = accb[o];
            bb = fmaf(xv.x, W4.x, bb);
            bb = fmaf(xv.y, W4.y, bb);
            bb = fmaf(xv.z, W4.z, bb);
            bb = fmaf(xv.w, W4.w, bb);
            accb[o] = bb;
        }
    }

    // ---- epilogue: out = wavelet + silu(base), vectorized store ----
    float* op = out + (size_t)n * ODIM + o0;
    #pragma unroll
    for (int ob = 0; ob < OT / 4; ob++) {
        float4 res;
        float* rp = (float*)&res;
        #pragma unroll
        for (int j = 0; j < 4; j++) {
            int o = ob * 4 + j;
            float b = accb[o];
            float t = ex2f(-1.44269504f * b);
            float sig = __frcp_rn(1.0f + t);
            rp[j] = fmaf(b, sig, accw[o].x + accw[o].y);
        }
        ((float4*)op)[ob] = res;
    }
}

extern "C" void kernel_launch(void* const* d_in, const int* in_sizes, int n_in,
                              void* d_out, int out_size) {
    const float* x     = (const float*)d_in[0];
    const float* scale = (const float*)d_in[1];
    const float* trans = (const float*)d_in[2];
    const float* ww    = (const float*)d_in[3];
    const float* bw    = (const float*)d_in[4];
    const float* gamma = (const float*)d_in[5];
    const float* beta  = (const float*)d_in[6];
    float* out = (float*)d_out;

    dim3 grid(NTOK / THREADS, ODIM / OT);
    wavekan_fused<<<grid, THREADS>>>(x, scale, trans, ww, bw, gamma, beta, out);
}